// round 13
// baseline (speedup 1.0000x reference)
#include <cuda_runtime.h>
#include <cuda_bf16.h>
#include <math_constants.h>

#define NM 1024
#define HH 256
#define WW 256
#define HW (HH * WW)
#define NQ 16            // stats partial chunks per mask
#define GRID 592         // 148 SMs * 4 resident blocks (guaranteed by launch_bounds)
#define NITEMS 24576     // 16384 stats items + 8192 zero items

// Scratch (no cudaMalloc allowed).
__device__ unsigned g_pp[NQ * NM];   // packed bbox: (rmin,255-rmax,cmin,255-cmax); 0xFFFFFFFF = empty
__device__ unsigned g_pk[NQ * NM];   // packed counts: hi<<16 | lo
__device__ float    g_gated[NM];
__device__ int      g_klist[NM];
__device__ int      g_kcnt;
__device__ unsigned g_arrive = 0;            // reset by nms block every launch
__device__ volatile unsigned g_flag = 0;     // monotonic generation counter

// ---------------------------------------------------------------------------
// ONE persistent kernel: phase 1 (fused stats-read + zero-write, period-3
// mix), device barrier (last block runs NMS), phase 3 (kept-mask sigmoid).
// ---------------------------------------------------------------------------
__global__ void __launch_bounds__(256, 4)
sam_persistent_kernel(const float* __restrict__ logits,
                      float* __restrict__ out,
                      const float* __restrict__ iou,
                      float* __restrict__ out_keep,
                      float* __restrict__ out_boxes,
                      int write_extra) {
    // ---- NMS shared state (allocated always; used by the last block) ----
    __shared__ float4 s_bx[NM];
    __shared__ float  s_csc[NM];
    __shared__ int    s_cid[NM];
    __shared__ float  s_sc[NM];
    __shared__ int    s_ord[NM];
    __shared__ float  s_area[NM];
    __shared__ unsigned s_sup[256 * 8];
    __shared__ unsigned s_live[8];
    __shared__ unsigned char s_keep[NM];
    __shared__ int s_cnt, s_kc, s_last;
    __shared__ unsigned s_p[8], s_pk[8];

    const int tid = threadIdx.x;
    const unsigned F0 = g_flag;   // generation at launch (all prior work drained)

    // ================= Phase 1: fused read/write streams =================
    for (int item = blockIdx.x; item < NITEMS; item += GRID) {
        const int rol = item % 3;
        const int grp = item / 3;

        if (rol == 2) {
            // ---- zero-writer role: 32 KB ----
            const int n    = grp & (NM - 1);
            const int half = grp >> 10;
            float4* __restrict__ o4 =
                reinterpret_cast<float4*>(out + (size_t)n * HW + (size_t)half * 8192);
            const float4 z = make_float4(0.f, 0.f, 0.f, 0.f);
#pragma unroll
            for (int k = 0; k < 8; k++) o4[k * 256 + tid] = z;
            continue;
        }

        // ---- stats role: 16 rows of one mask ----
        const int sidx = grp * 2 + rol;
        const int n    = sidx & (NM - 1);
        const int q    = sidx >> 10;
        const int tx   = tid & 63;
        const int ty   = tid >> 6;
        const int col0 = tx * 4;
        const int r0   = q * 16 + ty * 4;

        const float4* __restrict__ base =
            reinterpret_cast<const float4*>(logits + (size_t)n * HW) + tx;

        float4 v0 = base[(size_t)(r0 + 0) * (WW / 4)];
        float4 v1 = base[(size_t)(r0 + 1) * (WW / 4)];
        float4 v2 = base[(size_t)(r0 + 2) * (WW / 4)];
        float4 v3 = base[(size_t)(r0 + 3) * (WW / 4)];

        unsigned pk = 0;
        int rmin_t = 255, rmax_t = 0;
        unsigned cm4 = 0;

#define PROC(v, r)                                                             \
        {                                                                      \
            float mn = fminf(fminf(v.x, v.y), fminf(v.z, v.w));                \
            float mx = fmaxf(fmaxf(v.x, v.y), fmaxf(v.z, v.w));                \
            if (mx > -1.f) {                                                   \
                if (mn > 1.f) {                                                \
                    pk += 0x00040004u;                                         \
                    rmin_t = min(rmin_t, r);                                   \
                    rmax_t = r;                                                \
                    cm4 |= 0xFu;                                               \
                } else {                                                       \
                    int h = (v.x > 1.f) + (v.y > 1.f) + (v.z > 1.f) +          \
                            (v.w > 1.f);                                       \
                    int l = (v.x > -1.f) + (v.y > -1.f) + (v.z > -1.f) +       \
                            (v.w > -1.f);                                      \
                    pk += ((unsigned)h << 16) + (unsigned)l;                   \
                    unsigned m = (v.x > 0.f) | ((v.y > 0.f) << 1) |            \
                                 ((v.z > 0.f) << 2) | ((v.w > 0.f) << 3);      \
                    if (m) {                                                   \
                        rmin_t = min(rmin_t, r);                               \
                        rmax_t = r;                                            \
                        cm4 |= m;                                              \
                    }                                                          \
                }                                                              \
            }                                                                  \
        }

        PROC(v0, r0 + 0)
        PROC(v1, r0 + 1)
        PROC(v2, r0 + 2)
        PROC(v3, r0 + 3)
#undef PROC

        unsigned p;
        if (cm4) {
            int cmin_t = col0 + (__ffs(cm4) - 1);
            int cmax_t = col0 + (31 - __clz(cm4));
            p = ((unsigned)rmin_t << 24) | ((unsigned)(255 - rmax_t) << 16) |
                ((unsigned)cmin_t << 8) | (unsigned)(255 - cmax_t);
        } else {
            p = 0xFFFFFFFFu;
        }

#pragma unroll
        for (int o = 16; o > 0; o >>= 1) {
            p  = __vminu4(p, __shfl_down_sync(0xffffffffu, p, o));
            pk += __shfl_down_sync(0xffffffffu, pk, o);
        }

        const int warp = tid >> 5;
        if ((tid & 31) == 0) { s_p[warp] = p; s_pk[warp] = pk; }
        __syncthreads();
        if (tid == 0) {
            unsigned P = s_p[0], K = s_pk[0];
#pragma unroll
            for (int w = 1; w < 8; w++) { P = __vminu4(P, s_p[w]); K += s_pk[w]; }
            const int gidx = q * NM + n;
            g_pp[gidx] = P;
            g_pk[gidx] = K;
        }
        __syncthreads();   // protect s_p/s_pk reuse on next stats item
    }

    // ================= Device-wide barrier (sense-reversal) =================
    __threadfence();
    __syncthreads();
    if (tid == 0) {
        unsigned prev = atomicAdd(&g_arrive, 1u);
        s_last = (prev == GRID - 1) ? 1 : 0;
    }
    __syncthreads();

    if (s_last) {
        // ================= NMS by the last-arriving block (256 thr) =========
        if (tid == 0) { s_cnt = 0; s_kc = 0; }
        __syncthreads();

#pragma unroll
        for (int w = 0; w < 4; w++) {
            const int m = tid + w * 256;
            unsigned P = 0xFFFFFFFFu, K = 0;
#pragma unroll
            for (int q = 0; q < NQ; q++) {
                const int idx = q * NM + m;
                P = __vminu4(P, g_pp[idx]);
                K += g_pk[idx];
            }
            const int hi = (int)(K >> 16);
            const int lo = (int)(K & 0xFFFFu);

            float4 box;
            if (P == 0xFFFFFFFFu) {
                box = make_float4(0.f, 0.f, 0.f, 0.f);
            } else {
                box = make_float4((float)((P >> 8) & 0xFF),
                                  (float)(P >> 24),
                                  (float)(255 - (P & 0xFF)),
                                  (float)(255 - ((P >> 16) & 0xFF)));
            }
            s_bx[m] = box;

            const float ip   = iou[m];
            const float stab = (float)hi / fmaxf((float)lo, 1.0f);
            const bool  valid = (ip > 0.88f) && (stab >= 0.95f);
            if (valid) {
                int pos = atomicAdd(&s_cnt, 1);
                s_csc[pos] = ip;
                s_cid[pos] = m;
            }
            // defaults (overridden below for kept masks, ordered by syncthreads)
            g_gated[m] = 0.f;
            if (write_extra) {
                out_keep[m] = 0.f;
                reinterpret_cast<float4*>(out_boxes)[m] = box;
            }
        }
        __syncthreads();
        const int V = s_cnt;

        if (V > 0) {
            // O(V^2) rank (deterministic, desc score / asc idx)
            for (int c = tid; c < V; c += 256) {
                const float ms = s_csc[c];
                const int   mi = s_cid[c];
                int rank = 0;
                for (int j = 0; j < V; j++) {
                    float sj = s_csc[j];
                    rank += (sj > ms) | ((sj == ms) & (s_cid[j] < mi));
                }
                s_sc[rank] = ms;
                s_ord[rank] = mi;
            }
            __syncthreads();

            for (int c = tid; c < V; c += 256) {
                float4 b = s_bx[s_ord[c]];
                s_area[c] = fmaxf(b.z - b.x, 0.f) * fmaxf(b.w - b.y, 0.f);
            }
            __syncthreads();

            if (V <= 256) {
                if (tid < V) {
                    const float4 bi = s_bx[s_ord[tid]];
                    const float  ai = s_area[tid];
                    unsigned w[8] = {0, 0, 0, 0, 0, 0, 0, 0};
                    for (int j = tid + 1; j < V; j++) {
                        const float4 bj = s_bx[s_ord[j]];
                        float x0 = fmaxf(bi.x, bj.x), y0 = fmaxf(bi.y, bj.y);
                        float x1 = fminf(bi.z, bj.z), y1 = fminf(bi.w, bj.w);
                        float inter = fmaxf(x1 - x0, 0.f) * fmaxf(y1 - y0, 0.f);
                        float v = inter / fmaxf(ai + s_area[j] - inter, 1e-6f);
                        if (v > 0.7f) w[j >> 5] |= 1u << (j & 31);
                    }
#pragma unroll
                    for (int k = 0; k < 8; k++) s_sup[tid * 8 + k] = w[k];
                }
                __syncthreads();

                if (tid == 0) {
                    unsigned live[8];
#pragma unroll
                    for (int k = 0; k < 8; k++) {
                        int rem = V - k * 32;
                        live[k] = (rem >= 32) ? 0xffffffffu
                                              : (rem > 0 ? ((1u << rem) - 1u) : 0u);
                    }
                    for (int i = 0; i < V; i++) {
                        if ((live[i >> 5] >> (i & 31)) & 1u) {
#pragma unroll
                            for (int k = 0; k < 8; k++) live[k] &= ~s_sup[i * 8 + k];
                        }
                    }
#pragma unroll
                    for (int k = 0; k < 8; k++) s_live[k] = live[k];
                }
                __syncthreads();
                if (tid < V)
                    s_keep[tid] = (s_live[tid >> 5] >> (tid & 31)) & 1u;
            } else {
                // fallback: iterative greedy, candidates strided (rare)
                for (int c = tid; c < V; c += 256) s_keep[c] = 1;
                __syncthreads();
                for (int i = 0; i < V; i++) {
                    if (s_keep[i]) {
                        const float4 pb = s_bx[s_ord[i]];
                        const float  pa = s_area[i];
                        for (int c = tid; c < V; c += 256) {
                            if (c > i && s_keep[c]) {
                                const float4 mb = s_bx[s_ord[c]];
                                float x0 = fmaxf(pb.x, mb.x), y0 = fmaxf(pb.y, mb.y);
                                float x1 = fminf(pb.z, mb.z), y1 = fminf(pb.w, mb.w);
                                float inter = fmaxf(x1 - x0, 0.f) * fmaxf(y1 - y0, 0.f);
                                float v = inter / fmaxf(pa + s_area[c] - inter, 1e-6f);
                                if (v > 0.7f) s_keep[c] = 0;
                            }
                        }
                    }
                    __syncthreads();
                }
            }
            __syncthreads();

            // kept overrides + kept list (disjoint regions -> order-free)
            for (int c = tid; c < V; c += 256) {
                if (s_keep[c]) {
                    const int oi = s_ord[c];
                    g_gated[oi] = s_sc[c];
                    if (write_extra) out_keep[oi] = 1.f;
                    const int slot = atomicAdd(&s_kc, 1);
                    g_klist[slot] = oi;
                }
            }
        }
        __syncthreads();
        if (tid == 0) { g_kcnt = s_kc; g_arrive = 0; }

        // publish: every thread fences its writes, then tid0 bumps the flag
        __threadfence();
        __syncthreads();
        if (tid == 0) atomicExch((unsigned*)&g_flag, F0 + 1);
    } else {
        if (tid == 0) {
            while (g_flag == F0) __nanosleep(64);
        }
        __syncthreads();
        __threadfence();
    }

    // ================= Phase 3: kept-mask sigmoid pass =================
    const int kc = g_kcnt;
    for (int s = blockIdx.x; s < kc * 16; s += GRID) {
        const int n = g_klist[s >> 4];
        const float g = g_gated[n];
        const size_t base = (size_t)n * HW + (size_t)(s & 15) * 4096;
        const float4* __restrict__ in4 = reinterpret_cast<const float4*>(logits + base);
        float4* __restrict__ o4 = reinterpret_cast<float4*>(out + base);

#pragma unroll
        for (int k = 0; k < 4; k++) {
            float4 v = in4[k * 256 + tid];
            float4 r;
            r.x = g / (1.f + __expf(-v.x));
            r.y = g / (1.f + __expf(-v.y));
            r.z = g / (1.f + __expf(-v.z));
            r.w = g / (1.f + __expf(-v.w));
            o4[k * 256 + tid] = r;
        }
    }
}

// ---------------------------------------------------------------------------
extern "C" void kernel_launch(void* const* d_in, const int* in_sizes, int n_in,
                              void* d_out, int out_size) {
    const float* logits = (const float*)d_in[0];
    const float* iou    = (const float*)d_in[1];
    if (n_in >= 2 && in_sizes[0] == NM && in_sizes[1] == NM * HW) {
        logits = (const float*)d_in[1];
        iou    = (const float*)d_in[0];
    }

    float* out = (float*)d_out;
    const long long NHW = (long long)NM * HW;
    int write_extra = (out_size >= NHW + NM + NM * 4) ? 1 : 0;
    float* out_keep  = out + NHW;
    float* out_boxes = out + NHW + NM;

    sam_persistent_kernel<<<GRID, 256>>>(logits, out, iou, out_keep, out_boxes, write_extra);
}